// round 1
// baseline (speedup 1.0000x reference)
#include <cuda_runtime.h>

// MatrixReconstructionLayer: per-row fundamental-matrix construction.
// X[B,8] = [f1,f2,rx,ry,rz,tx,ty,tz] -> F[B,9] (row-major 3x3).
//
// F = K2inv @ T @ R @ K1inv, with R = Rx@Ry@Rz expanded in closed form.
// HBM-bound: 128MiB in + 144MiB out. Output staged through shared memory so
// the 9-float row stride still produces fully coalesced 128B store wavefronts.

#define EPSF 1e-8f
#define TPB 256

__global__ __launch_bounds__(TPB)
void fmat_kernel(const float* __restrict__ X, float* __restrict__ out, int B) {
    __shared__ float s[TPB * 9];

    const int tid = threadIdx.x;
    const long long row = (long long)blockIdx.x * TPB + tid;

    if (row < B) {
        // Row = 32 bytes = two aligned float4 loads.
        const float4* Xv = reinterpret_cast<const float4*>(X);
        float4 a = Xv[row * 2 + 0];   // f1, f2, rx, ry
        float4 b = Xv[row * 2 + 1];   // rz, tx, ty, tz

        const float f1 = a.x, f2 = a.y, rx = a.z, ry = a.w;
        const float rz = b.x, tx = b.y, ty = b.z, tz = b.w;

        float sx, cx, sy, cy, sz, cz;
        sincosf(rx, &sx, &cx);
        sincosf(ry, &sy, &cy);
        sincosf(rz, &sz, &cz);

        const float k1 = -1.0f / (f1 + EPSF);
        const float k2 = -1.0f / (f2 + EPSF);

        // R = Rx @ (Ry @ Rz), expanded.
        const float sxsy = sx * sy;
        const float cxsy = cx * sy;

        const float r00 = cy * cz;
        const float r01 = -cy * sz;
        const float r02 = -sy;
        const float r10 = cx * sz - sxsy * cz;
        const float r11 = cx * cz + sxsy * sz;
        const float r12 = -sx * cy;
        const float r20 = sx * sz + cxsy * cz;
        const float r21 = sx * cz - cxsy * sz;
        const float r22 = cx * cy;

        // M = T @ R  (T = skew(t)); rows of M are combinations of rows of R.
        const float m00 = ty * r20 - tz * r10;
        const float m01 = ty * r21 - tz * r11;
        const float m02 = ty * r22 - tz * r12;
        const float m10 = tz * r00 - tx * r20;
        const float m11 = tz * r01 - tx * r21;
        const float m12 = tz * r02 - tx * r22;
        const float m20 = tx * r10 - ty * r00;
        const float m21 = tx * r11 - ty * r01;
        const float m22 = tx * r12 - ty * r02;

        // F = diag(k2,k2,1) @ M @ diag(k1,k1,1)
        float* sr = &s[tid * 9];   // stride 9 vs 32 banks: gcd=1, conflict-free
        sr[0] = k2 * m00 * k1;
        sr[1] = k2 * m01 * k1;
        sr[2] = k2 * m02;
        sr[3] = k2 * m10 * k1;
        sr[4] = k2 * m11 * k1;
        sr[5] = k2 * m12;
        sr[6] = m20 * k1;
        sr[7] = m21 * k1;
        sr[8] = m22;
    }

    __syncthreads();

    // Coalesced block-contiguous store: block covers TPB*9 consecutive floats.
    const long long base = (long long)blockIdx.x * (TPB * 9);
    const long long total = (long long)B * 9;
#pragma unroll
    for (int k = 0; k < 9; k++) {
        long long idx = base + k * TPB + tid;
        if (idx < total) out[idx] = s[k * TPB + tid];
    }
}

extern "C" void kernel_launch(void* const* d_in, const int* in_sizes, int n_in,
                              void* d_out, int out_size) {
    const float* X = (const float*)d_in[0];
    float* out = (float*)d_out;
    const int B = in_sizes[0] / 8;
    const int blocks = (B + TPB - 1) / TPB;
    fmat_kernel<<<blocks, TPB>>>(X, out, B);
}

// round 2
// speedup vs baseline: 1.0544x; 1.0544x over previous
#include <cuda_runtime.h>

// MatrixReconstructionLayer: X[B,8]=[f1,f2,rx,ry,rz,tx,ty,tz] -> F[B,9] (3x3 row-major).
// F = K2inv @ T @ R @ K1inv, closed-form. HBM-bound target: ~300MB @ ~6.8TB/s.
// Output staged through smem, copied out as float4 (fully coalesced STG.128).

#define EPSF 1e-8f
#define TPB 256

__device__ __forceinline__ void compute_row(const float4 a, const float4 b, float* sr) {
    const float f1 = a.x, f2 = a.y, rx = a.z, ry = a.w;
    const float rz = b.x, tx = b.y, ty = b.z, tz = b.w;

    float sx, cx, sy, cy, sz, cz;
    sincosf(rx, &sx, &cx);
    sincosf(ry, &sy, &cy);
    sincosf(rz, &sz, &cz);

    const float k1 = -1.0f / (f1 + EPSF);
    const float k2 = -1.0f / (f2 + EPSF);

    // R = Rx @ (Ry @ Rz)
    const float sxsy = sx * sy;
    const float cxsy = cx * sy;

    const float r00 = cy * cz;
    const float r01 = -cy * sz;
    const float r02 = -sy;
    const float r10 = cx * sz - sxsy * cz;
    const float r11 = cx * cz + sxsy * sz;
    const float r12 = -sx * cy;
    const float r20 = sx * sz + cxsy * cz;
    const float r21 = sx * cz - cxsy * sz;
    const float r22 = cx * cy;

    // M = skew(t) @ R
    const float m00 = ty * r20 - tz * r10;
    const float m01 = ty * r21 - tz * r11;
    const float m02 = ty * r22 - tz * r12;
    const float m10 = tz * r00 - tx * r20;
    const float m11 = tz * r01 - tx * r21;
    const float m12 = tz * r02 - tx * r22;
    const float m20 = tx * r10 - ty * r00;
    const float m21 = tx * r11 - ty * r01;
    const float m22 = tx * r12 - ty * r02;

    // F = diag(k2,k2,1) @ M @ diag(k1,k1,1)
    const float k21 = k2 * k1;
    sr[0] = k21 * m00;
    sr[1] = k21 * m01;
    sr[2] = k2 * m02;
    sr[3] = k21 * m10;
    sr[4] = k21 * m11;
    sr[5] = k2 * m12;
    sr[6] = m20 * k1;
    sr[7] = m21 * k1;
    sr[8] = m22;
}

// Fast path: B % TPB == 0. 32-bit indexing, no predicates except the 64-float4 tail
// of the block copy. Streaming cache hints (data touched exactly once).
__global__ __launch_bounds__(TPB)
void fmat_kernel_fast(const float* __restrict__ X, float* __restrict__ out) {
    __shared__ __align__(16) float s[TPB * 9];

    const int tid = threadIdx.x;
    const unsigned row = blockIdx.x * TPB + tid;

    const float4* Xv = reinterpret_cast<const float4*>(X);
    const float4 a = __ldcs(&Xv[row * 2 + 0]);
    const float4 b = __ldcs(&Xv[row * 2 + 1]);

    compute_row(a, b, &s[tid * 9]);   // stride 9: gcd(9,32)=1, conflict-free

    __syncthreads();

    // Block output: TPB*9 = 2304 floats = 576 float4. Copy vectorized.
    const float4* s4 = reinterpret_cast<const float4*>(s);
    float4* out4 = reinterpret_cast<float4*>(out) + (unsigned)blockIdx.x * 576u;
    __stcs(&out4[tid],        s4[tid]);
    __stcs(&out4[tid + 256],  s4[tid + 256]);
    if (tid < 64)
        __stcs(&out4[tid + 512], s4[tid + 512]);
}

// Generic fallback (any B): scalar coalesced stores via smem.
__global__ __launch_bounds__(TPB)
void fmat_kernel_gen(const float* __restrict__ X, float* __restrict__ out, int B) {
    __shared__ float s[TPB * 9];
    const int tid = threadIdx.x;
    const long long row = (long long)blockIdx.x * TPB + tid;

    if (row < B) {
        const float4* Xv = reinterpret_cast<const float4*>(X);
        float4 a = Xv[row * 2 + 0];
        float4 b = Xv[row * 2 + 1];
        compute_row(a, b, &s[tid * 9]);
    }
    __syncthreads();

    const long long base = (long long)blockIdx.x * (TPB * 9);
    const long long total = (long long)B * 9;
#pragma unroll
    for (int k = 0; k < 9; k++) {
        long long idx = base + k * TPB + tid;
        if (idx < total) out[idx] = s[k * TPB + tid];
    }
}

extern "C" void kernel_launch(void* const* d_in, const int* in_sizes, int n_in,
                              void* d_out, int out_size) {
    const float* X = (const float*)d_in[0];
    float* out = (float*)d_out;
    const int B = in_sizes[0] / 8;
    if (B % TPB == 0) {
        fmat_kernel_fast<<<B / TPB, TPB>>>(X, out);
    } else {
        fmat_kernel_gen<<<(B + TPB - 1) / TPB, TPB>>>(X, out, B);
    }
}